// round 4
// baseline (speedup 1.0000x reference)
#include <cuda_runtime.h>
#include <cstdint>

// MixtureCrossattention: per batch b,
//   C = [e1 | e2]  (16 x 576),  e = patch_embed(x)
//   x3[:,q] = sum_p lam3(p) * softmax_p(e2[:,q]·C[:,p]) * C[:,p]   (lam3 = 0.7 for p<288 else 0.3)
//   x4[:,q] = sum_p lam4(p) * softmax_p(e1[:,q]·C[:,p]) * C[:,p]   (lam4 = 0.3 for p<288 else 0.7)
// (the reference's batch-0 block-transpose is a no-op: the e2^T e2 block is symmetric)
//
// One CTA per batch. 288 threads; thread t serves TWO queries:
//   q0 = column 288+t (x3 output column t), q1 = column t (x4 output column t).
// Keys loaded from smem once per 2-column row, reused for 2 queries x (score+accum):
// 64 fma2 per 8 LDS -> latency convoy amortized.
// lambda folded into exponent bias: w = 2^(s*log2e + log2 lam) = lam * e^s.

#define LOG2E   1.4426950408889634f
#define LOG2_07 (-0.5145731728297583f)
#define LOG2_03 (-1.7369655941662063f)

typedef unsigned long long ull;

__device__ __forceinline__ ull pack2(float lo, float hi) {
    ull r; asm("mov.b64 %0, {%1, %2};" : "=l"(r) : "f"(lo), "f"(hi)); return r;
}
__device__ __forceinline__ void unpack2(ull v, float &lo, float &hi) {
    asm("mov.b64 {%0, %1}, %2;" : "=f"(lo), "=f"(hi) : "l"(v));
}
__device__ __forceinline__ ull fma2(ull a, ull b, ull c) {
    ull d; asm("fma.rn.f32x2 %0, %1, %2, %3;" : "=l"(d) : "l"(a), "l"(b), "l"(c)); return d;
}
__device__ __forceinline__ float ex2a(float x) {
    float y; asm("ex2.approx.f32 %0, %1;" : "=f"(y) : "f"(x)); return y;
}

__global__ __launch_bounds__(288, 2)
void mixca_kernel(const float* __restrict__ x1,
                  const float* __restrict__ x2,
                  float* __restrict__ out)
{
    // sK[j*16 + i] = C[i][j], j = key column 0..575, i = dim 0..15
    __shared__ __align__(16) float sK[576 * 16];

    const int b = blockIdx.x;
    const int t = threadIdx.x;   // 0..287

    // ---- Load + patch-embed both inputs into sK ----
    {
        const float* src0 = x1 + (size_t)b * 4608;
        const float* src1 = x2 + (size_t)b * 4608;
        #pragma unroll
        for (int e = 0; e < 2; e++) {
            const float* src = (e == 0) ? src0 : src1;
            #pragma unroll
            for (int k = 0; k < 16; k++) {
                int g = t + k * 288;           // linear idx into [32][12][12]
                float v = src[g];
                int c   = g / 144;
                int rem = g - c * 144;
                int r   = rem / 12;
                int s   = rem - r * 12;
                int h = r / 3, p1 = r - h * 3;
                int w = s / 3, p2 = s - w * 3;
                int i = h * 4 + w;                        // 0..15
                int j = (p1 * 3 + p2) * 32 + c + e * 288; // 0..575
                sK[j * 16 + i] = v;
            }
        }
    }
    __syncthreads();

    // ---- Two query vectors, dims packed in pairs, pre-scaled by log2(e) ----
    ull qv0[8], qv1[8];     // qv0: column 288+t (x3), qv1: column t (x4)
    {
        const float4* qp0 = reinterpret_cast<const float4*>(&sK[(288 + t) * 16]);
        const float4* qp1 = reinterpret_cast<const float4*>(&sK[t * 16]);
        #pragma unroll
        for (int u = 0; u < 4; u++) {
            float4 q0 = qp0[u];
            float4 q1 = qp1[u];
            qv0[2 * u]     = pack2(q0.x * LOG2E, q0.y * LOG2E);
            qv0[2 * u + 1] = pack2(q0.z * LOG2E, q0.w * LOG2E);
            qv1[2 * u]     = pack2(q1.x * LOG2E, q1.y * LOG2E);
            qv1[2 * u + 1] = pack2(q1.z * LOG2E, q1.w * LOG2E);
        }
    }

    ull acc0[8], acc1[8];
    #pragma unroll
    for (int i = 0; i < 8; i++) { acc0[i] = 0ull; acc1[i] = 0ull; }
    float sw0s0 = 0.f, sw0s1 = 0.f;   // half0 lam-weighted exp sums per segment
    float sw1s0 = 0.f, sw1s1 = 0.f;   // half1

    #pragma unroll
    for (int seg = 0; seg < 2; seg++) {
        // half0 (x3): lam 0.7 on e1 keys (seg0), 0.3 on e2 keys (seg1)
        // half1 (x4): lam 0.3 on e1 keys (seg0), 0.7 on e2 keys (seg1)
        const ull bias0 = pack2(seg ? LOG2_03 : LOG2_07, 0.0f);
        const ull bias1 = pack2(seg ? LOG2_07 : LOG2_03, 0.0f);
        float s0 = 0.f, s1 = 0.f;
        #pragma unroll 1
        for (int jp = seg * 144; jp < seg * 144 + 144; jp++) {
            // two key columns (2jp, 2jp+1): 32 contiguous floats, loaded ONCE
            const ulonglong2* row = reinterpret_cast<const ulonglong2*>(&sK[jp * 32]);
            ulonglong2 a0 = row[0], a1 = row[1], a2 = row[2], a3 = row[3];
            ulonglong2 b0 = row[4], b1 = row[5], b2 = row[6], b3 = row[7];

            // 4 score chains: (query0|query1) x (keyA|keyB)
            ull s0A = fma2(qv0[0], a0.x, bias0);
            ull s0B = fma2(qv0[0], b0.x, bias0);
            ull s1A = fma2(qv1[0], a0.x, bias1);
            ull s1B = fma2(qv1[0], b0.x, bias1);
            s0A = fma2(qv0[1], a0.y, s0A);  s0B = fma2(qv0[1], b0.y, s0B);
            s1A = fma2(qv1[1], a0.y, s1A);  s1B = fma2(qv1[1], b0.y, s1B);
            s0A = fma2(qv0[2], a1.x, s0A);  s0B = fma2(qv0[2], b1.x, s0B);
            s1A = fma2(qv1[2], a1.x, s1A);  s1B = fma2(qv1[2], b1.x, s1B);
            s0A = fma2(qv0[3], a1.y, s0A);  s0B = fma2(qv0[3], b1.y, s0B);
            s1A = fma2(qv1[3], a1.y, s1A);  s1B = fma2(qv1[3], b1.y, s1B);
            s0A = fma2(qv0[4], a2.x, s0A);  s0B = fma2(qv0[4], b2.x, s0B);
            s1A = fma2(qv1[4], a2.x, s1A);  s1B = fma2(qv1[4], b2.x, s1B);
            s0A = fma2(qv0[5], a2.y, s0A);  s0B = fma2(qv0[5], b2.y, s0B);
            s1A = fma2(qv1[5], a2.y, s1A);  s1B = fma2(qv1[5], b2.y, s1B);
            s0A = fma2(qv0[6], a3.x, s0A);  s0B = fma2(qv0[6], b3.x, s0B);
            s1A = fma2(qv1[6], a3.x, s1A);  s1B = fma2(qv1[6], b3.x, s1B);
            s0A = fma2(qv0[7], a3.y, s0A);  s0B = fma2(qv0[7], b3.y, s0B);
            s1A = fma2(qv1[7], a3.y, s1A);  s1B = fma2(qv1[7], b3.y, s1B);

            float lo, hi;
            unpack2(s0A, lo, hi);  float w0A = ex2a(lo + hi);
            unpack2(s0B, lo, hi);  float w0B = ex2a(lo + hi);
            unpack2(s1A, lo, hi);  float w1A = ex2a(lo + hi);
            unpack2(s1B, lo, hi);  float w1B = ex2a(lo + hi);
            s0 += w0A;  s0 += w0B;
            s1 += w1A;  s1 += w1B;
            ull w0A2 = pack2(w0A, w0A);
            ull w0B2 = pack2(w0B, w0B);
            ull w1A2 = pack2(w1A, w1A);
            ull w1B2 = pack2(w1B, w1B);

            acc0[0] = fma2(w0A2, a0.x, acc0[0]);  acc0[0] = fma2(w0B2, b0.x, acc0[0]);
            acc1[0] = fma2(w1A2, a0.x, acc1[0]);  acc1[0] = fma2(w1B2, b0.x, acc1[0]);
            acc0[1] = fma2(w0A2, a0.y, acc0[1]);  acc0[1] = fma2(w0B2, b0.y, acc0[1]);
            acc1[1] = fma2(w1A2, a0.y, acc1[1]);  acc1[1] = fma2(w1B2, b0.y, acc1[1]);
            acc0[2] = fma2(w0A2, a1.x, acc0[2]);  acc0[2] = fma2(w0B2, b1.x, acc0[2]);
            acc1[2] = fma2(w1A2, a1.x, acc1[2]);  acc1[2] = fma2(w1B2, b1.x, acc1[2]);
            acc0[3] = fma2(w0A2, a1.y, acc0[3]);  acc0[3] = fma2(w0B2, b1.y, acc0[3]);
            acc1[3] = fma2(w1A2, a1.y, acc1[3]);  acc1[3] = fma2(w1B2, b1.y, acc1[3]);
            acc0[4] = fma2(w0A2, a2.x, acc0[4]);  acc0[4] = fma2(w0B2, b2.x, acc0[4]);
            acc1[4] = fma2(w1A2, a2.x, acc1[4]);  acc1[4] = fma2(w1B2, b2.x, acc1[4]);
            acc0[5] = fma2(w0A2, a2.y, acc0[5]);  acc0[5] = fma2(w0B2, b2.y, acc0[5]);
            acc1[5] = fma2(w1A2, a2.y, acc1[5]);  acc1[5] = fma2(w1B2, b2.y, acc1[5]);
            acc0[6] = fma2(w0A2, a3.x, acc0[6]);  acc0[6] = fma2(w0B2, b3.x, acc0[6]);
            acc1[6] = fma2(w1A2, a3.x, acc1[6]);  acc1[6] = fma2(w1B2, b3.x, acc1[6]);
            acc0[7] = fma2(w0A2, a3.y, acc0[7]);  acc0[7] = fma2(w0B2, b3.y, acc0[7]);
            acc1[7] = fma2(w1A2, a3.y, acc1[7]);  acc1[7] = fma2(w1B2, b3.y, acc1[7]);
        }
        if (seg == 0) { sw0s0 = s0; sw1s0 = s1; }
        else          { sw0s1 = s0; sw1s1 = s1; }
    }

    // denominators: sum e^s = sw_seg0/lam_seg0 + sw_seg1/lam_seg1
    const float inv0 = 1.0f / (sw0s0 * (1.0f / 0.7f) + sw0s1 * (1.0f / 0.3f));
    const float inv1 = 1.0f / (sw1s0 * (1.0f / 0.3f) + sw1s1 * (1.0f / 0.7f));

    // ---- Stage + coalesced un-patch store, one half at a time ----
    float* sO = sK;   // reuse as [288][17]
    float* dst0 = out + (size_t)b * 4608;
    float* dst1 = out + (size_t)(512 + b) * 4608;

    #pragma unroll
    for (int half = 0; half < 2; half++) {
        __syncthreads();   // sK free (or previous half's stores consumed)
        const ull* acc = (half == 0) ? acc0 : acc1;
        const float inv = (half == 0) ? inv0 : inv1;
        #pragma unroll
        for (int u = 0; u < 8; u++) {
            float lo, hi;
            unpack2(acc[u], lo, hi);
            sO[t * 17 + 2 * u]     = lo * inv;
            sO[t * 17 + 2 * u + 1] = hi * inv;
        }
        __syncthreads();
        float* dst = (half == 0) ? dst0 : dst1;
        #pragma unroll
        for (int k = 0; k < 16; k++) {
            int g = t + k * 288;
            int c   = g / 144;
            int rem = g - c * 144;
            int r   = rem / 12;
            int s   = rem - r * 12;
            int h = r / 3, p1 = r - h * 3;
            int w = s / 3, p2 = s - w * 3;
            int i  = h * 4 + w;
            int tt = (p1 * 3 + p2) * 32 + c;
            dst[g] = sO[tt * 17 + i];
        }
    }
}

extern "C" void kernel_launch(void* const* d_in, const int* in_sizes, int n_in,
                              void* d_out, int out_size)
{
    const float* x1 = (const float*)d_in[0];
    const float* x2 = (const float*)d_in[1];
    float* out = (float*)d_out;
    mixca_kernel<<<512, 288>>>(x1, x2, out);
}

// round 5
// speedup vs baseline: 1.0246x; 1.0246x over previous
#include <cuda_runtime.h>
#include <cstdint>

// MixtureCrossattention: per batch b,
//   C = [e1 | e2]  (16 x 576),  e = patch_embed(x)
//   x3[:,q] = sum_p lam3(p) * softmax_p(e2[:,q]·C[:,p]) * C[:,p]   (lam3 = 0.7 for p<288 else 0.3)
//   x4[:,q] = sum_p lam4(p) * softmax_p(e1[:,q]·C[:,p]) * C[:,p]   (lam4 = 0.3 for p<288 else 0.7)
// (the reference's batch-0 block-transpose is a no-op: the e2^T e2 block is symmetric)
//
// One CTA per (batch, half), 288 threads, ONE query per thread (register-safe).
// 2-stage software pipeline over single keys: load+score of key j+1 overlaps
// ex2+accumulate of key j, so the MUFU latency and score-chain gaps are hidden.
// lambda folded into exponent bias: w = 2^(s*log2e + log2 lam) = lam * e^s.

#define LOG2E   1.4426950408889634f
#define LOG2_07 (-0.5145731728297583f)
#define LOG2_03 (-1.7369655941662063f)

typedef unsigned long long ull;

__device__ __forceinline__ ull pack2(float lo, float hi) {
    ull r; asm("mov.b64 %0, {%1, %2};" : "=l"(r) : "f"(lo), "f"(hi)); return r;
}
__device__ __forceinline__ void unpack2(ull v, float &lo, float &hi) {
    asm("mov.b64 {%0, %1}, %2;" : "=f"(lo), "=f"(hi) : "l"(v));
}
__device__ __forceinline__ ull fma2(ull a, ull b, ull c) {
    ull d; asm("fma.rn.f32x2 %0, %1, %2, %3;" : "=l"(d) : "l"(a), "l"(b), "l"(c)); return d;
}
__device__ __forceinline__ float ex2a(float x) {
    float y; asm("ex2.approx.f32 %0, %1;" : "=f"(y) : "f"(x)); return y;
}

// score for one key (16 dims in K[0..3], dim pairs in lanes), bias pre-folded
__device__ __forceinline__ ull score8(const ulonglong2* K, const ull* qv, ull bias2) {
    ull s = fma2(qv[0], K[0].x, bias2);
    s = fma2(qv[1], K[0].y, s);
    s = fma2(qv[2], K[1].x, s);
    s = fma2(qv[3], K[1].y, s);
    s = fma2(qv[4], K[2].x, s);
    s = fma2(qv[5], K[2].y, s);
    s = fma2(qv[6], K[3].x, s);
    s = fma2(qv[7], K[3].y, s);
    return s;
}

__device__ __forceinline__ void accum8(ull* acc, const ulonglong2* K, ull w2) {
    acc[0] = fma2(w2, K[0].x, acc[0]);
    acc[1] = fma2(w2, K[0].y, acc[1]);
    acc[2] = fma2(w2, K[1].x, acc[2]);
    acc[3] = fma2(w2, K[1].y, acc[3]);
    acc[4] = fma2(w2, K[2].x, acc[4]);
    acc[5] = fma2(w2, K[2].y, acc[5]);
    acc[6] = fma2(w2, K[3].x, acc[6]);
    acc[7] = fma2(w2, K[3].y, acc[7]);
}

__global__ __launch_bounds__(288, 2)
void mixca_kernel(const float* __restrict__ x1,
                  const float* __restrict__ x2,
                  float* __restrict__ out)
{
    // sK[j*16 + i] = C[i][j], j = key column 0..575, i = dim 0..15
    __shared__ __align__(16) float sK[576 * 16];

    const int b    = blockIdx.x;
    const int half = blockIdx.y;   // 0 -> x3, 1 -> x4
    const int t    = threadIdx.x;  // query 0..287

    // ---- Load + patch-embed both inputs into sK ----
    {
        const float* src0 = x1 + (size_t)b * 4608;
        const float* src1 = x2 + (size_t)b * 4608;
        #pragma unroll
        for (int e = 0; e < 2; e++) {
            const float* src = (e == 0) ? src0 : src1;
            #pragma unroll
            for (int k = 0; k < 16; k++) {
                int g = t + k * 288;           // linear idx into [32][12][12]
                float v = src[g];
                int c   = g / 144;
                int rem = g - c * 144;
                int r   = rem / 12;
                int s   = rem - r * 12;
                int h = r / 3, p1 = r - h * 3;
                int w = s / 3, p2 = s - w * 3;
                int i = h * 4 + w;                        // 0..15
                int j = (p1 * 3 + p2) * 32 + c + e * 288; // 0..575
                sK[j * 16 + i] = v;
            }
        }
    }
    __syncthreads();

    // ---- Query vector: dims packed in pairs, pre-scaled by log2(e) ----
    const int qcol = (half == 0) ? (288 + t) : t;   // x3 uses e2 queries, x4 uses e1
    ull qv[8];
    {
        const float4* qp = reinterpret_cast<const float4*>(&sK[qcol * 16]);
        #pragma unroll
        for (int u = 0; u < 4; u++) {
            float4 q = qp[u];
            qv[2 * u]     = pack2(q.x * LOG2E, q.y * LOG2E);
            qv[2 * u + 1] = pack2(q.z * LOG2E, q.w * LOG2E);
        }
    }

    ull acc[8];
    #pragma unroll
    for (int i = 0; i < 8; i++) acc[i] = 0ull;
    float sw0 = 0.0f, sw1 = 0.0f;

    const float biasA = (half == 0) ? LOG2_07 : LOG2_03;  // keys 0..287 (e1)
    const float biasB = (half == 0) ? LOG2_03 : LOG2_07;  // keys 288..575 (e2)

    #pragma unroll 1
    for (int seg = 0; seg < 2; seg++) {
        const ull bias2 = pack2(seg ? biasB : biasA, 0.0f);
        float sw = 0.0f;
        const ulonglong2* base =
            reinterpret_cast<const ulonglong2*>(&sK[seg * 288 * 16]);

        ulonglong2 K[2][4];
        ull sc[2];

        // prologue: key 0
        #pragma unroll
        for (int u = 0; u < 4; u++) K[0][u] = base[u];
        sc[0] = score8(K[0], qv, bias2);

        // 2-stage pipeline: prefetch+score key c+1, finish (ex2+accum) key c
        #pragma unroll 2
        for (int c = 0; c < 287; c++) {
            const int cur = c & 1, nxt = cur ^ 1;
            #pragma unroll
            for (int u = 0; u < 4; u++) K[nxt][u] = base[(c + 1) * 4 + u];
            sc[nxt] = score8(K[nxt], qv, bias2);

            float lo, hi;
            unpack2(sc[cur], lo, hi);
            float w = ex2a(lo + hi);      // = lam * e^{score}
            sw += w;
            ull w2 = pack2(w, w);
            accum8(acc, K[cur], w2);
        }
        // epilogue: key 287 lives in buffer 1 (287 & 1)
        {
            float lo, hi;
            unpack2(sc[1], lo, hi);
            float w = ex2a(lo + hi);
            sw += w;
            ull w2 = pack2(w, w);
            accum8(acc, K[1], w2);
        }
        if (seg == 0) sw0 = sw; else sw1 = sw;
    }

    // denominator: sum e^s = sw0/lamA + sw1/lamB
    const float invLamA = (half == 0) ? (1.0f / 0.7f) : (1.0f / 0.3f);
    const float invLamB = (half == 0) ? (1.0f / 0.3f) : (1.0f / 0.7f);
    const float inv = 1.0f / (sw0 * invLamA + sw1 * invLamB);

    __syncthreads();          // everyone done reading sK; reuse as staging
    float* sO = sK;           // [288][17] padded
    #pragma unroll
    for (int u = 0; u < 8; u++) {
        float lo, hi;
        unpack2(acc[u], lo, hi);
        sO[t * 17 + 2 * u]     = lo * inv;
        sO[t * 17 + 2 * u + 1] = hi * inv;
    }
    __syncthreads();

    // ---- Coalesced un-patch store: out layout (x3 block, then x4 block) ----
    float* dst = out + ((size_t)half * 512 + (size_t)b) * 4608;
    #pragma unroll
    for (int k = 0; k < 16; k++) {
        int g = t + k * 288;
        int c   = g / 144;
        int rem = g - c * 144;
        int r   = rem / 12;
        int s   = rem - r * 12;
        int h = r / 3, p1 = r - h * 3;
        int w = s / 3, p2 = s - w * 3;
        int i  = h * 4 + w;
        int tt = (p1 * 3 + p2) * 32 + c;
        dst[g] = sO[tt * 17 + i];
    }
}

extern "C" void kernel_launch(void* const* d_in, const int* in_sizes, int n_in,
                              void* d_out, int out_size)
{
    const float* x1 = (const float*)d_in[0];
    const float* x2 = (const float*)d_in[1];
    float* out = (float*)d_out;
    dim3 grid(512, 2);
    mixca_kernel<<<grid, 288>>>(x1, x2, out);
}

// round 8
// speedup vs baseline: 1.1052x; 1.0787x over previous
#include <cuda_runtime.h>
#include <cstdint>

// MixtureCrossattention: per batch b,
//   C = [e1 | e2]  (16 x 576),  e = patch_embed(x)
//   x3[:,q] = sum_p lam3(p) * softmax_p(e2[:,q]·C[:,p]) * C[:,p]   (lam3 = 0.7 for p<288 else 0.3)
//   x4[:,q] = sum_p lam4(p) * softmax_p(e1[:,q]·C[:,p]) * C[:,p]   (lam4 = 0.3 for p<288 else 0.7)
// (the reference's batch-0 block-transpose is a no-op: the e2^T e2 block is symmetric)
//
// One CTA per (batch, half), 288 threads, ONE query per thread.
// Register-lean (target <=74 regs) so 3 CTAs fit per SM -> 27 warps for latency hiding.
// Keys single-buffered in registers; lambda folded into exponent bias:
// w = 2^(s*log2e + log2 lam) = lam * e^s.

#define LOG2E   1.4426950408889634f
#define LOG2_07 (-0.5145731728297583f)
#define LOG2_03 (-1.7369655941662063f)

typedef unsigned long long ull;

__device__ __forceinline__ ull pack2(float lo, float hi) {
    ull r; asm("mov.b64 %0, {%1, %2};" : "=l"(r) : "f"(lo), "f"(hi)); return r;
}
__device__ __forceinline__ void unpack2(ull v, float &lo, float &hi) {
    asm("mov.b64 {%0, %1}, %2;" : "=f"(lo), "=f"(hi) : "l"(v));
}
__device__ __forceinline__ ull fma2(ull a, ull b, ull c) {
    ull d; asm("fma.rn.f32x2 %0, %1, %2, %3;" : "=l"(d) : "l"(a), "l"(b), "l"(c)); return d;
}
__device__ __forceinline__ float ex2a(float x) {
    float y; asm("ex2.approx.f32 %0, %1;" : "=f"(y) : "f"(x)); return y;
}

__global__ __launch_bounds__(288, 3)
void mixca_kernel(const float* __restrict__ x1,
                  const float* __restrict__ x2,
                  float* __restrict__ out)
{
    // sK[j*16 + i] = C[i][j], j = key column 0..575, i = dim 0..15
    __shared__ __align__(16) float sK[576 * 16];

    const int b    = blockIdx.x;
    const int half = blockIdx.y;   // 0 -> x3, 1 -> x4
    const int t    = threadIdx.x;  // query 0..287

    // ---- Load + patch-embed both inputs into sK ----
    {
        const float* src0 = x1 + (size_t)b * 4608;
        const float* src1 = x2 + (size_t)b * 4608;
        #pragma unroll
        for (int e = 0; e < 2; e++) {
            const float* src = (e == 0) ? src0 : src1;
            #pragma unroll
            for (int k = 0; k < 16; k++) {
                int g = t + k * 288;           // linear idx into [32][12][12]
                float v = src[g];
                int c   = g / 144;
                int rem = g - c * 144;
                int r   = rem / 12;
                int s   = rem - r * 12;
                int h = r / 3, p1 = r - h * 3;
                int w = s / 3, p2 = s - w * 3;
                int i = h * 4 + w;                        // 0..15
                int j = (p1 * 3 + p2) * 32 + c + e * 288; // 0..575
                sK[j * 16 + i] = v;
            }
        }
    }
    __syncthreads();

    // ---- Query vector: dims packed in pairs, pre-scaled by log2(e) ----
    const int qcol = (half == 0) ? (288 + t) : t;   // x3 uses e2 queries, x4 uses e1
    ull qv[8];
    {
        const float4* qp = reinterpret_cast<const float4*>(&sK[qcol * 16]);
        #pragma unroll
        for (int u = 0; u < 4; u++) {
            float4 q = qp[u];
            qv[2 * u]     = pack2(q.x * LOG2E, q.y * LOG2E);
            qv[2 * u + 1] = pack2(q.z * LOG2E, q.w * LOG2E);
        }
    }

    ull acc[8];
    #pragma unroll
    for (int i = 0; i < 8; i++) acc[i] = 0ull;
    float sw0 = 0.0f, sw1 = 0.0f;

    const float biasA = (half == 0) ? LOG2_07 : LOG2_03;  // keys 0..287 (e1)
    const float biasB = (half == 0) ? LOG2_03 : LOG2_07;  // keys 288..575 (e2)

    #pragma unroll 1
    for (int seg = 0; seg < 2; seg++) {
        const ull bias2 = pack2(seg ? biasB : biasA, 0.0f);
        float sw = 0.0f;
        const ulonglong2* base =
            reinterpret_cast<const ulonglong2*>(&sK[seg * 288 * 16]);

        #pragma unroll 1
        for (int c = 0; c < 288; c++) {
            // one key column: 16 dims, single-buffered in regs
            ulonglong2 k0 = base[c * 4 + 0];
            ulonglong2 k1 = base[c * 4 + 1];
            ulonglong2 k2 = base[c * 4 + 2];
            ulonglong2 k3 = base[c * 4 + 3];

            ull s = fma2(qv[0], k0.x, bias2);
            s = fma2(qv[1], k0.y, s);
            s = fma2(qv[2], k1.x, s);
            s = fma2(qv[3], k1.y, s);
            s = fma2(qv[4], k2.x, s);
            s = fma2(qv[5], k2.y, s);
            s = fma2(qv[6], k3.x, s);
            s = fma2(qv[7], k3.y, s);

            float lo, hi;
            unpack2(s, lo, hi);
            float w = ex2a(lo + hi);     // = lam * e^{score}
            sw += w;
            ull w2 = pack2(w, w);

            acc[0] = fma2(w2, k0.x, acc[0]);
            acc[1] = fma2(w2, k0.y, acc[1]);
            acc[2] = fma2(w2, k1.x, acc[2]);
            acc[3] = fma2(w2, k1.y, acc[3]);
            acc[4] = fma2(w2, k2.x, acc[4]);
            acc[5] = fma2(w2, k2.y, acc[5]);
            acc[6] = fma2(w2, k3.x, acc[6]);
            acc[7] = fma2(w2, k3.y, acc[7]);
        }
        if (seg == 0) sw0 = sw; else sw1 = sw;
    }

    // denominator: sum e^s = sw0/lamA + sw1/lamB
    const float invLamA = (half == 0) ? (1.0f / 0.7f) : (1.0f / 0.3f);
    const float invLamB = (half == 0) ? (1.0f / 0.3f) : (1.0f / 0.7f);
    const float inv = 1.0f / (sw0 * invLamA + sw1 * invLamB);

    __syncthreads();          // everyone done reading sK; reuse as staging
    float* sO = sK;           // [288][17] padded
    #pragma unroll
    for (int u = 0; u < 8; u++) {
        float lo, hi;
        unpack2(acc[u], lo, hi);
        sO[t * 17 + 2 * u]     = lo * inv;
        sO[t * 17 + 2 * u + 1] = hi * inv;
    }
    __syncthreads();

    // ---- Coalesced un-patch store: out layout (x3 block, then x4 block) ----
    float* dst = out + ((size_t)half * 512 + (size_t)b) * 4608;
    #pragma unroll
    for (int k = 0; k < 16; k++) {
        int g = t + k * 288;
        int c   = g / 144;
        int rem = g - c * 144;
        int r   = rem / 12;
        int s   = rem - r * 12;
        int h = r / 3, p1 = r - h * 3;
        int w = s / 3, p2 = s - w * 3;
        int i  = h * 4 + w;
        int tt = (p1 * 3 + p2) * 32 + c;
        dst[g] = sO[tt * 17 + i];
    }
}

extern "C" void kernel_launch(void* const* d_in, const int* in_sizes, int n_in,
                              void* d_out, int out_size)
{
    const float* x1 = (const float*)d_in[0];
    const float* x2 = (const float*)d_in[1];
    float* out = (float*)d_out;
    dim3 grid(512, 2);
    mixca_kernel<<<grid, 288>>>(x1, x2, out);
}